// round 1
// baseline (speedup 1.0000x reference)
#include <cuda_runtime.h>
#include <cuda_bf16.h>

// Problem constants: B=2, H=1, LQ=LK=512, D=64, HID=128
#define NB   2
#define L    512
#define DD   64
#define HID  128

// Scratch (allocation-free rule: __device__ globals)
__device__ float g_vp[NB * L * DD];            // projected V
__device__ float g_qaqb[NB * L * HID * 2];     // interleaved (qa, qb) per (row, h)
__device__ float g_kbka[NB * L * HID * 2];     // interleaved (kb+b1, ka+b1) per (row, h)

// ---------------------------------------------------------------------------
// Kernel A: projections + pairwise-MLP feature precompute.
// grid = NB * (L/4) = 256 blocks, 256 threads. Each block: 4 q-rows + 4 k-rows.
// ---------------------------------------------------------------------------
__global__ __launch_bounds__(256) void prep_kernel(
    const float* __restrict__ q, const float* __restrict__ k,
    const float* __restrict__ v, const float* __restrict__ Ww,
    const float* __restrict__ wb, const float* __restrict__ W1,
    const float* __restrict__ b1)
{
    __shared__ float q_s[4][DD], k_s[4][DD], v_s[4][DD];
    __shared__ float qp_s[4][DD], kp_s[4][DD];

    const int tid  = threadIdx.x;
    const int b    = blockIdx.x >> 7;          // / 128
    const int r0   = (blockIdx.x & 127) * 4;   // first row of the 4-row tile
    const int base = (b * L + r0) * DD;        // element offset of row r0

    // Stage 4 rows of q, k, v (256 floats each == blockDim)
    {
        int r = tid >> 6, e = tid & 63;
        q_s[r][e] = q[base + tid];
        k_s[r][e] = k[base + tid];
        v_s[r][e] = v[base + tid];
    }
    __syncthreads();

    // Projections: qp = q@Ww+wb, kp = k@Ww+wb, vp = v@Ww+wb
    {
        int pj = tid >> 6, d = tid & 63;
        if (pj < 3) {
            const float (*src)[DD] = (pj == 0) ? q_s : (pj == 1) ? k_s : v_s;
            float acc[4];
            float bias = wb[d];
            #pragma unroll
            for (int r = 0; r < 4; r++) acc[r] = bias;
            #pragma unroll 8
            for (int e = 0; e < DD; e++) {
                float w = Ww[e * DD + d];
                #pragma unroll
                for (int r = 0; r < 4; r++) acc[r] += src[r][e] * w;
            }
            #pragma unroll
            for (int r = 0; r < 4; r++) {
                if (pj == 0)      qp_s[r][d] = acc[r];
                else if (pj == 1) kp_s[r][d] = acc[r];
                else              g_vp[base + r * DD + d] = acc[r];
            }
        }
    }
    __syncthreads();

    // Features:
    //   half==0 (tid<128):  qa[h] = qp·W1q[:,h],  qb[h] = qp·W1k[:,h]
    //   half==1 (tid>=128): ka[h] = kp·W1q[:,h]+b1, kb[h] = kp·W1k[:,h]+b1
    {
        int half = tid >> 7;
        int h    = tid & 127;
        const float (*src)[DD] = half ? kp_s : qp_s;
        float accA[4] = {0.f, 0.f, 0.f, 0.f};   // · W1q
        float accB[4] = {0.f, 0.f, 0.f, 0.f};   // · W1k
        #pragma unroll 8
        for (int e = 0; e < DD; e++) {
            float w1q = W1[e * HID + h];
            float w1k = W1[(DD + e) * HID + h];
            #pragma unroll
            for (int r = 0; r < 4; r++) {
                float x = src[r][e];
                accA[r] += x * w1q;
                accB[r] += x * w1k;
            }
        }
        float bb = b1[h];
        #pragma unroll
        for (int r = 0; r < 4; r++) {
            int off = ((b * L + r0 + r) * HID + h) * 2;
            if (!half) {
                g_qaqb[off + 0] = accA[r];        // qa
                g_qaqb[off + 1] = accB[r];        // qb
            } else {
                g_kbka[off + 0] = accB[r] + bb;   // kb + b1
                g_kbka[off + 1] = accA[r] + bb;   // ka + b1
            }
        }
    }
}

// ---------------------------------------------------------------------------
// Kernel B: pairwise scores + softmax + attn@vp + output projection.
// grid = NB * (L/4) = 256 blocks, 128 threads = 4 warps; warp w owns row i.
// ---------------------------------------------------------------------------
__global__ __launch_bounds__(128) void attn_kernel(
    const float* __restrict__ mask, const float* __restrict__ Wd,
    const float* __restrict__ db,   const float* __restrict__ W2,
    const float* __restrict__ b2,   float* __restrict__ out)
{
    __shared__ float qq_s[4][HID * 2];   // (qa,qb) interleaved per warp-row
    __shared__ float w2_s[HID];
    __shared__ float attn_s[4][L];
    __shared__ float o_s[4][DD];

    const int tid  = threadIdx.x;
    const int warp = tid >> 5;
    const int lane = tid & 31;
    const int b     = blockIdx.x >> 7;
    const int itile = blockIdx.x & 127;
    const int i     = itile * 4 + warp;
    const int row   = b * L + i;

    // Stage qa/qb for the 4 rows + W2
    for (int x = tid; x < 4 * HID * 2; x += 128)
        ((float*)qq_s)[x] = g_qaqb[(b * L + itile * 4) * (HID * 2) + x];
    if (tid < HID) w2_s[tid] = W2[tid];
    __syncthreads();

    const float b2v = b2[0];
    const float4* qq4 = (const float4*)qq_s[warp];

    float s[16];
    #pragma unroll 1
    for (int jc = 0; jc < 16; jc++) {
        int j = jc * 32 + lane;
        const float4* kk4 = (const float4*)(g_kbka + (b * L + j) * (HID * 2));
        float acc = 0.f;
        #pragma unroll 8
        for (int hh = 0; hh < HID / 2; hh++) {
            float4 kk = __ldg(kk4 + hh);           // (kb[2h], ka[2h], kb[2h+1], ka[2h+1])
            float4 qv = qq4[hh];                    // (qa[2h], qb[2h], qa[2h+1], qb[2h+1])
            float2 ww = ((const float2*)w2_s)[hh];  // (w2[2h], w2[2h+1])
            acc += fmaxf(kk.x + qv.x, 0.f) * ww.x;  // branch 1, h=2hh
            acc += fmaxf(kk.y + qv.y, 0.f) * ww.x;  // branch 2, h=2hh
            acc += fmaxf(kk.z + qv.z, 0.f) * ww.y;  // branch 1, h=2hh+1
            acc += fmaxf(kk.w + qv.w, 0.f) * ww.y;  // branch 2, h=2hh+1
        }
        s[jc] = acc + 2.f * b2v + mask[row * L + j] * (-1e9f);
    }

    // Softmax over the 512 scores of this row (16 regs per lane + warp reduce)
    float m = s[0];
    #pragma unroll
    for (int jc = 1; jc < 16; jc++) m = fmaxf(m, s[jc]);
    #pragma unroll
    for (int o = 16; o > 0; o >>= 1) m = fmaxf(m, __shfl_xor_sync(0xffffffffu, m, o));
    float sum = 0.f;
    #pragma unroll
    for (int jc = 0; jc < 16; jc++) { s[jc] = __expf(s[jc] - m); sum += s[jc]; }
    #pragma unroll
    for (int o = 16; o > 0; o >>= 1) sum += __shfl_xor_sync(0xffffffffu, sum, o);
    float inv = 1.f / sum;

    float* arow = attn_s[warp];
    float* aout = out + NB * L * DD + row * L;   // attn region follows out region
    #pragma unroll
    for (int jc = 0; jc < 16; jc++) {
        float a = s[jc] * inv;
        arow[jc * 32 + lane] = a;
        aout[jc * 32 + lane] = a;
    }
    __syncwarp();

    // attn @ vp  (lane owns dims 2*lane, 2*lane+1)
    float ox = 0.f, oy = 0.f;
    const float2* vp2 = (const float2*)(g_vp + b * L * DD);
    #pragma unroll 4
    for (int j = 0; j < L; j++) {
        float a = arow[j];
        float2 vv = __ldg(vp2 + j * 32 + lane);
        ox += a * vv.x;
        oy += a * vv.y;
    }
    o_s[warp][2 * lane]     = ox;
    o_s[warp][2 * lane + 1] = oy;
    __syncwarp();

    // final projection: out = o @ Wd + db
    int d0 = 2 * lane;
    float f0 = db[d0], f1 = db[d0 + 1];
    const float2* Wd2 = (const float2*)Wd;
    #pragma unroll 8
    for (int e = 0; e < DD; e++) {
        float ov = o_s[warp][e];
        float2 wv = __ldg(Wd2 + e * 32 + lane);
        f0 += ov * wv.x;
        f1 += ov * wv.y;
    }
    out[row * DD + d0]     = f0;
    out[row * DD + d0 + 1] = f1;
}

// ---------------------------------------------------------------------------
// Inputs (metadata order): q, k, v, mask, Ww, wb, Wd, db, W1, b1, W2, b2
// Output: [out (B,H,LQ,D) | attn (B,H,LQ,LK)] as float32
// ---------------------------------------------------------------------------
extern "C" void kernel_launch(void* const* d_in, const int* in_sizes, int n_in,
                              void* d_out, int out_size)
{
    const float* q    = (const float*)d_in[0];
    const float* k    = (const float*)d_in[1];
    const float* v    = (const float*)d_in[2];
    const float* mask = (const float*)d_in[3];
    const float* Ww   = (const float*)d_in[4];
    const float* wb   = (const float*)d_in[5];
    const float* Wd   = (const float*)d_in[6];
    const float* db   = (const float*)d_in[7];
    const float* W1   = (const float*)d_in[8];
    const float* b1   = (const float*)d_in[9];
    const float* W2   = (const float*)d_in[10];
    const float* b2   = (const float*)d_in[11];
    float* out = (float*)d_out;

    prep_kernel<<<NB * (L / 4), 256>>>(q, k, v, Ww, wb, W1, b1);
    attn_kernel<<<NB * (L / 4), 128>>>(mask, Wd, db, W2, b2, out);
}

// round 3
// speedup vs baseline: 1.8702x; 1.8702x over previous
#include <cuda_runtime.h>
#include <cuda_bf16.h>

// Problem constants: B=2, H=1, LQ=LK=512, D=64, HID=128
#define NB   2
#define L    512
#define DD   64
#define HID  128

// Scratch (allocation-free rule: __device__ globals)
__device__ float  g_vp[NB * L * DD];             // projected V
__device__ float  g_qaqb[NB * L * HID * 2];      // interleaved (qa, qb) per (row, h)
__device__ float2 g_kbkaT[NB * HID * L];         // TRANSPOSED: [b][h][j] -> (kb+b1, ka+b1)

// ---------------------------------------------------------------------------
// Kernel A: projections + pairwise-MLP feature precompute.
// grid = NB * (L/4) = 256 blocks, 256 threads. Each block: 4 q-rows + 4 k-rows.
// ---------------------------------------------------------------------------
__global__ __launch_bounds__(256) void prep_kernel(
    const float* __restrict__ q, const float* __restrict__ k,
    const float* __restrict__ v, const float* __restrict__ Ww,
    const float* __restrict__ wb, const float* __restrict__ W1,
    const float* __restrict__ b1)
{
    __shared__ float q_s[4][DD], k_s[4][DD], v_s[4][DD];
    __shared__ float qp_s[4][DD], kp_s[4][DD];

    const int tid  = threadIdx.x;
    const int b    = blockIdx.x >> 7;          // / 128
    const int r0   = (blockIdx.x & 127) * 4;   // first row of the 4-row tile
    const int base = (b * L + r0) * DD;        // element offset of row r0

    // Stage 4 rows of q, k, v (256 floats each == blockDim)
    {
        int r = tid >> 6, e = tid & 63;
        q_s[r][e] = q[base + tid];
        k_s[r][e] = k[base + tid];
        v_s[r][e] = v[base + tid];
    }
    __syncthreads();

    // Projections: qp = q@Ww+wb, kp = k@Ww+wb, vp = v@Ww+wb
    {
        int pj = tid >> 6, d = tid & 63;
        if (pj < 3) {
            const float (*src)[DD] = (pj == 0) ? q_s : (pj == 1) ? k_s : v_s;
            float acc[4];
            float bias = wb[d];
            #pragma unroll
            for (int r = 0; r < 4; r++) acc[r] = bias;
            #pragma unroll 8
            for (int e = 0; e < DD; e++) {
                float w = Ww[e * DD + d];
                #pragma unroll
                for (int r = 0; r < 4; r++) acc[r] += src[r][e] * w;
            }
            #pragma unroll
            for (int r = 0; r < 4; r++) {
                if (pj == 0)      qp_s[r][d] = acc[r];
                else if (pj == 1) kp_s[r][d] = acc[r];
                else              g_vp[base + r * DD + d] = acc[r];
            }
        }
    }
    __syncthreads();

    // Features:
    //   half==0 (tid<128):  qa[h] = qp·W1q[:,h],  qb[h] = qp·W1k[:,h]
    //   half==1 (tid>=128): ka[h] = kp·W1q[:,h]+b1, kb[h] = kp·W1k[:,h]+b1
    {
        int half = tid >> 7;
        int h    = tid & 127;
        const float (*src)[DD] = half ? kp_s : qp_s;
        float accA[4] = {0.f, 0.f, 0.f, 0.f};   // · W1q
        float accB[4] = {0.f, 0.f, 0.f, 0.f};   // · W1k
        #pragma unroll 8
        for (int e = 0; e < DD; e++) {
            float w1q = W1[e * HID + h];
            float w1k = W1[(DD + e) * HID + h];
            #pragma unroll
            for (int r = 0; r < 4; r++) {
                float x = src[r][e];
                accA[r] += x * w1q;
                accB[r] += x * w1k;
            }
        }
        float bb = b1[h];
        #pragma unroll
        for (int r = 0; r < 4; r++) {
            if (!half) {
                int off = ((b * L + r0 + r) * HID + h) * 2;
                g_qaqb[off + 0] = accA[r];        // qa
                g_qaqb[off + 1] = accB[r];        // qb
            } else {
                // transposed layout [b][h][j]
                g_kbkaT[(b * HID + h) * L + (r0 + r)] =
                    make_float2(accB[r] + bb, accA[r] + bb);   // (kb+b1, ka+b1)
            }
        }
    }
}

// ---------------------------------------------------------------------------
// Kernel B: pairwise scores + softmax + attn@vp + output projection.
// grid = NB*(L/4) = 256 blocks, 256 threads = 8 warps.
// warp w: iw = w&3 selects the i-row within the 4-row tile,
//         jhalf = w>>2 selects which half of the 512 j-columns it scores.
// ---------------------------------------------------------------------------
__global__ __launch_bounds__(256) void attn_kernel(
    const float* __restrict__ mask, const float* __restrict__ Wd,
    const float* __restrict__ db,   const float* __restrict__ W2,
    const float* __restrict__ b2,   float* __restrict__ out)
{
    __shared__ float qq_s[4][HID * 2];   // (qa,qb) interleaved per i-row
    __shared__ float w2_s[HID];
    __shared__ float attn_s[4][L];
    __shared__ float red_a[8], red_b[8];
    __shared__ float o_part[4][DD];

    const int tid   = threadIdx.x;
    const int warp  = tid >> 5;
    const int lane  = tid & 31;
    const int iw    = warp & 3;
    const int jhalf = warp >> 2;
    const int b     = blockIdx.x >> 7;
    const int itile = blockIdx.x & 127;
    const int i     = itile * 4 + iw;
    const int row   = b * L + i;

    // Stage qa/qb for the 4 rows + W2
    for (int x = tid; x < 4 * HID * 2; x += 256)
        ((float*)qq_s)[x] = g_qaqb[(b * L + itile * 4) * (HID * 2) + x];
    if (tid < HID) w2_s[tid] = W2[tid];
    __syncthreads();

    // ---- scores: warp covers j = [jhalf*256, jhalf*256+256), lane owns j-pairs
    // float4 view of kbkaT row h: element jp covers j = 2*jp, 2*jp+1
    const float4* ktbase = reinterpret_cast<const float4*>(g_kbkaT + (size_t)(b * HID) * L);
    const float2* qq2    = (const float2*)qq_s[iw];

    float acc[4][2];
    #pragma unroll
    for (int c = 0; c < 4; c++) { acc[c][0] = 0.f; acc[c][1] = 0.f; }

    #pragma unroll 2
    for (int h = 0; h < HID; h++) {
        float2 qv = qq2[h];                    // (qa, qb) — warp-uniform LDS
        float  w2 = w2_s[h];
        const float4* kt = ktbase + h * (L / 2);
        #pragma unroll
        for (int c = 0; c < 4; c++) {
            float4 kk = __ldg(kt + jhalf * 128 + c * 32 + lane);  // (kb,ka) x 2 j
            acc[c][0] += (fmaxf(qv.x + kk.x, 0.f) + fmaxf(qv.y + kk.y, 0.f)) * w2;
            acc[c][1] += (fmaxf(qv.x + kk.z, 0.f) + fmaxf(qv.y + kk.w, 0.f)) * w2;
        }
    }

    // finalize scores: + 2*b2 + mask*(-1e9)
    const float b2v2 = 2.f * b2[0];
    const float2* mrow = (const float2*)(mask + (size_t)row * L);
    float s[4][2];
    #pragma unroll
    for (int c = 0; c < 4; c++) {
        int jp = jhalf * 128 + c * 32 + lane;
        float2 mm = __ldg(mrow + jp);
        s[c][0] = acc[c][0] + b2v2 + mm.x * (-1e9f);
        s[c][1] = acc[c][1] + b2v2 + mm.y * (-1e9f);
    }

    // ---- softmax across the 2 warps of this row
    float m = s[0][0];
    #pragma unroll
    for (int c = 0; c < 4; c++) { m = fmaxf(m, s[c][0]); m = fmaxf(m, s[c][1]); }
    #pragma unroll
    for (int o = 16; o > 0; o >>= 1) m = fmaxf(m, __shfl_xor_sync(0xffffffffu, m, o));
    if (lane == 0) red_a[warp] = m;
    __syncthreads();
    m = fmaxf(red_a[iw], red_a[iw + 4]);

    float sum = 0.f;
    #pragma unroll
    for (int c = 0; c < 4; c++) {
        s[c][0] = __expf(s[c][0] - m);
        s[c][1] = __expf(s[c][1] - m);
        sum += s[c][0] + s[c][1];
    }
    #pragma unroll
    for (int o = 16; o > 0; o >>= 1) sum += __shfl_xor_sync(0xffffffffu, sum, o);
    if (lane == 0) red_b[warp] = sum;
    __syncthreads();
    const float inv = 1.f / (red_b[iw] + red_b[iw + 4]);

    // write attn (own j-half) to smem + global
    float2* arow2 = (float2*)attn_s[iw];
    float2* aout2 = (float2*)(out + (size_t)NB * L * DD + (size_t)row * L);
    #pragma unroll
    for (int c = 0; c < 4; c++) {
        int jp = jhalf * 128 + c * 32 + lane;
        float2 a = make_float2(s[c][0] * inv, s[c][1] * inv);
        arow2[jp] = a;
        aout2[jp] = a;
    }
    __syncwarp();

    // ---- attn @ vp over own j-half (lane owns dims 2*lane, 2*lane+1)
    float ox = 0.f, oy = 0.f;
    const float2* vp2  = (const float2*)(g_vp + (size_t)b * L * DD);
    const float*  arow = attn_s[iw] + jhalf * 256;
    #pragma unroll 4
    for (int jj = 0; jj < 256; jj++) {
        float a = arow[jj];
        float2 vv = __ldg(vp2 + (jhalf * 256 + jj) * 32 + lane);
        ox += a * vv.x;
        oy += a * vv.y;
    }
    if (jhalf == 1) {
        o_part[iw][2 * lane]     = ox;
        o_part[iw][2 * lane + 1] = oy;
    }
    __syncthreads();

    if (jhalf == 0) {
        // combine halves into smem o-row
        float fox = ox + o_part[iw][2 * lane];
        float foy = oy + o_part[iw][2 * lane + 1];
        __syncwarp();
        o_part[iw][2 * lane]     = fox;
        o_part[iw][2 * lane + 1] = foy;
        __syncwarp();

        // final projection: out = o @ Wd + db
        int d0 = 2 * lane;
        float f0 = db[d0], f1 = db[d0 + 1];
        const float2* Wd2 = (const float2*)Wd;
        #pragma unroll 8
        for (int e = 0; e < DD; e++) {
            float ov = o_part[iw][e];
            float2 wv = __ldg(Wd2 + e * 32 + lane);
            f0 += ov * wv.x;
            f1 += ov * wv.y;
        }
        out[row * DD + d0]     = f0;
        out[row * DD + d0 + 1] = f1;
    }
}

// ---------------------------------------------------------------------------
// Inputs (metadata order): q, k, v, mask, Ww, wb, Wd, db, W1, b1, W2, b2
// Output: [out (B,H,LQ,D) | attn (B,H,LQ,LK)] as float32
// ---------------------------------------------------------------------------
extern "C" void kernel_launch(void* const* d_in, const int* in_sizes, int n_in,
                              void* d_out, int out_size)
{
    const float* q    = (const float*)d_in[0];
    const float* k    = (const float*)d_in[1];
    const float* v    = (const float*)d_in[2];
    const float* mask = (const float*)d_in[3];
    const float* Ww   = (const float*)d_in[4];
    const float* wb   = (const float*)d_in[5];
    const float* Wd   = (const float*)d_in[6];
    const float* db   = (const float*)d_in[7];
    const float* W1   = (const float*)d_in[8];
    const float* b1   = (const float*)d_in[9];
    const float* W2   = (const float*)d_in[10];
    const float* b2   = (const float*)d_in[11];
    float* out = (float*)d_out;

    prep_kernel<<<NB * (L / 4), 256>>>(q, k, v, Ww, wb, W1, b1);
    attn_kernel<<<NB * (L / 4), 256>>>(mask, Wd, db, W2, b2, out);
}

// round 4
// speedup vs baseline: 3.8304x; 2.0481x over previous
#include <cuda_runtime.h>
#include <cuda_bf16.h>

// Problem constants: B=2, H=1, LQ=LK=512, D=64, HID=128
#define NB   2
#define L    512
#define DD   64
#define HID  128

// Scratch (allocation-free rule: __device__ globals)
__device__ float  g_vp[NB * L * DD];             // projected V
__device__ float  g_qaqb[NB * L * HID * 2];      // interleaved (qa, qb) per (row, h)
__device__ float2 g_kbkaT[NB * HID * L];         // TRANSPOSED: [b][h][j] -> (kb+b1, ka+b1)

// ---------------------------------------------------------------------------
// Kernel A: projections + pairwise-MLP feature precompute.
// grid = NB * (L/4) = 256 blocks, 256 threads. Each block: 4 q-rows + 4 k-rows.
// ---------------------------------------------------------------------------
__global__ __launch_bounds__(256) void prep_kernel(
    const float* __restrict__ q, const float* __restrict__ k,
    const float* __restrict__ v, const float* __restrict__ Ww,
    const float* __restrict__ wb, const float* __restrict__ W1,
    const float* __restrict__ b1)
{
    __shared__ float q_s[4][DD], k_s[4][DD], v_s[4][DD];
    __shared__ float qp_s[4][DD], kp_s[4][DD];

    const int tid  = threadIdx.x;
    const int b    = blockIdx.x >> 7;          // / 128
    const int r0   = (blockIdx.x & 127) * 4;   // first row of the 4-row tile
    const int base = (b * L + r0) * DD;        // element offset of row r0

    // Stage 4 rows of q, k, v (256 floats each == blockDim)
    {
        int r = tid >> 6, e = tid & 63;
        q_s[r][e] = q[base + tid];
        k_s[r][e] = k[base + tid];
        v_s[r][e] = v[base + tid];
    }
    __syncthreads();

    // Projections: qp = q@Ww+wb, kp = k@Ww+wb, vp = v@Ww+wb
    {
        int pj = tid >> 6, d = tid & 63;
        if (pj < 3) {
            const float (*src)[DD] = (pj == 0) ? q_s : (pj == 1) ? k_s : v_s;
            float acc[4];
            float bias = wb[d];
            #pragma unroll
            for (int r = 0; r < 4; r++) acc[r] = bias;
            #pragma unroll 8
            for (int e = 0; e < DD; e++) {
                float w = Ww[e * DD + d];
                #pragma unroll
                for (int r = 0; r < 4; r++) acc[r] += src[r][e] * w;
            }
            #pragma unroll
            for (int r = 0; r < 4; r++) {
                if (pj == 0)      qp_s[r][d] = acc[r];
                else if (pj == 1) kp_s[r][d] = acc[r];
                else              g_vp[base + r * DD + d] = acc[r];
            }
        }
    }
    __syncthreads();

    // Features:
    //   half==0 (tid<128):  qa[h] = qp·W1q[:,h],  qb[h] = qp·W1k[:,h]
    //   half==1 (tid>=128): ka[h] = kp·W1q[:,h]+b1, kb[h] = kp·W1k[:,h]+b1
    {
        int half = tid >> 7;
        int h    = tid & 127;
        const float (*src)[DD] = half ? kp_s : qp_s;
        float accA[4] = {0.f, 0.f, 0.f, 0.f};   // · W1q
        float accB[4] = {0.f, 0.f, 0.f, 0.f};   // · W1k
        #pragma unroll 8
        for (int e = 0; e < DD; e++) {
            float w1q = W1[e * HID + h];
            float w1k = W1[(DD + e) * HID + h];
            #pragma unroll
            for (int r = 0; r < 4; r++) {
                float x = src[r][e];
                accA[r] += x * w1q;
                accB[r] += x * w1k;
            }
        }
        float bb = b1[h];
        #pragma unroll
        for (int r = 0; r < 4; r++) {
            if (!half) {
                int off = ((b * L + r0 + r) * HID + h) * 2;
                g_qaqb[off + 0] = accA[r];        // qa
                g_qaqb[off + 1] = accB[r];        // qb
            } else {
                // transposed layout [b][h][j]
                g_kbkaT[(b * HID + h) * L + (r0 + r)] =
                    make_float2(accB[r] + bb, accA[r] + bb);   // (kb+b1, ka+b1)
            }
        }
    }
}

// ---------------------------------------------------------------------------
// Kernel B: pairwise scores + softmax + attn@vp + output projection.
// grid = NB*(L/2) = 512 blocks, 256 threads = 8 warps.
// warp w: iw = w&1 selects the i-row within the 2-row tile,
//         jq = w>>1 selects the 128-wide j-quarter it scores.
// ---------------------------------------------------------------------------
__global__ __launch_bounds__(256, 2) void attn_kernel(
    const float* __restrict__ mask, const float* __restrict__ Wd,
    const float* __restrict__ db,   const float* __restrict__ W2,
    const float* __restrict__ b2,   float* __restrict__ out)
{
    __shared__ float qq_s[2][HID * 2];   // (qa,qb) interleaved per i-row
    __shared__ float w2_s[HID];
    __shared__ float attn_s[2][L];
    __shared__ float red_m[2][4], red_s[2][4];
    __shared__ float o_part[2][4][DD];

    const int tid   = threadIdx.x;
    const int warp  = tid >> 5;
    const int lane  = tid & 31;
    const int iw    = warp & 1;
    const int jq    = warp >> 1;
    const int b     = blockIdx.x >> 8;         // / 256
    const int itile = blockIdx.x & 255;
    const int i     = itile * 2 + iw;
    const int row   = b * L + i;

    // Stage qa/qb for the 2 rows + W2
    for (int x = tid; x < 2 * HID * 2; x += 256)
        ((float*)qq_s)[x] = g_qaqb[(b * L + itile * 2) * (HID * 2) + x];
    if (tid < HID) w2_s[tid] = W2[tid];
    __syncthreads();

    // ---- scores: warp covers j = [jq*128, jq*128+128), lane owns 2 j-pairs (4 j)
    // float4 view of kbkaT row h: element jp covers j = 2*jp, 2*jp+1
    const float4* ktbase = reinterpret_cast<const float4*>(g_kbkaT + (size_t)(b * HID) * L)
                         + jq * 64;
    const float2* qq2    = (const float2*)qq_s[iw];

    float acc[2][2];
    acc[0][0] = acc[0][1] = acc[1][0] = acc[1][1] = 0.f;

    #pragma unroll 4
    for (int h = 0; h < HID; h++) {
        float2 qv = qq2[h];                    // (qa, qb) — warp-uniform LDS broadcast
        float  w2 = w2_s[h];
        const float4* kt = ktbase + h * (L / 2);
        #pragma unroll
        for (int c = 0; c < 2; c++) {
            float4 kk = __ldg(kt + c * 32 + lane);  // (kb,ka) x 2 j
            acc[c][0] += (fmaxf(qv.x + kk.x, 0.f) + fmaxf(qv.y + kk.y, 0.f)) * w2;
            acc[c][1] += (fmaxf(qv.x + kk.z, 0.f) + fmaxf(qv.y + kk.w, 0.f)) * w2;
        }
    }

    // finalize scores: + 2*b2 + mask*(-1e9)
    const float b2v2 = 2.f * b2[0];
    const float2* mrow = (const float2*)(mask + (size_t)row * L) + jq * 64;
    float s[2][2];
    #pragma unroll
    for (int c = 0; c < 2; c++) {
        float2 mm = __ldg(mrow + c * 32 + lane);
        s[c][0] = acc[c][0] + b2v2 + mm.x * (-1e9f);
        s[c][1] = acc[c][1] + b2v2 + mm.y * (-1e9f);
    }

    // ---- softmax across the 4 warps of this row
    float m = fmaxf(fmaxf(s[0][0], s[0][1]), fmaxf(s[1][0], s[1][1]));
    #pragma unroll
    for (int o = 16; o > 0; o >>= 1) m = fmaxf(m, __shfl_xor_sync(0xffffffffu, m, o));
    if (lane == 0) red_m[iw][jq] = m;
    __syncthreads();
    m = fmaxf(fmaxf(red_m[iw][0], red_m[iw][1]), fmaxf(red_m[iw][2], red_m[iw][3]));

    float sum = 0.f;
    #pragma unroll
    for (int c = 0; c < 2; c++) {
        s[c][0] = __expf(s[c][0] - m);
        s[c][1] = __expf(s[c][1] - m);
        sum += s[c][0] + s[c][1];
    }
    #pragma unroll
    for (int o = 16; o > 0; o >>= 1) sum += __shfl_xor_sync(0xffffffffu, sum, o);
    if (lane == 0) red_s[iw][jq] = sum;
    __syncthreads();
    const float inv = 1.f / (red_s[iw][0] + red_s[iw][1] + red_s[iw][2] + red_s[iw][3]);

    // write attn (own j-quarter) to smem + global
    float2* arow2 = (float2*)attn_s[iw] + jq * 64;
    float2* aout2 = (float2*)(out + (size_t)NB * L * DD + (size_t)row * L) + jq * 64;
    #pragma unroll
    for (int c = 0; c < 2; c++) {
        int jp = c * 32 + lane;
        float2 a = make_float2(s[c][0] * inv, s[c][1] * inv);
        arow2[jp] = a;
        aout2[jp] = a;
    }
    __syncwarp();

    // ---- attn @ vp over own j-quarter (lane owns dims 2*lane, 2*lane+1)
    float ox = 0.f, oy = 0.f;
    const float2* vp2  = (const float2*)(g_vp + (size_t)b * L * DD);
    const float*  arow = attn_s[iw] + jq * 128;
    #pragma unroll 4
    for (int jj = 0; jj < 128; jj++) {
        float a = arow[jj];
        float2 vv = __ldg(vp2 + (jq * 128 + jj) * 32 + lane);
        ox += a * vv.x;
        oy += a * vv.y;
    }
    o_part[iw][jq][2 * lane]     = ox;
    o_part[iw][jq][2 * lane + 1] = oy;
    __syncthreads();

    if (jq == 0) {
        // combine the 4 quarters into the o-row (lane owns 2 dims)
        int d0 = 2 * lane;
        float fox = o_part[iw][0][d0]     + o_part[iw][1][d0]
                  + o_part[iw][2][d0]     + o_part[iw][3][d0];
        float foy = o_part[iw][0][d0 + 1] + o_part[iw][1][d0 + 1]
                  + o_part[iw][2][d0 + 1] + o_part[iw][3][d0 + 1];
        o_part[iw][0][d0]     = fox;
        o_part[iw][0][d0 + 1] = foy;
        __syncwarp();

        // final projection: out = o @ Wd + db
        float f0 = db[d0], f1 = db[d0 + 1];
        const float2* Wd2 = (const float2*)Wd;
        #pragma unroll 8
        for (int e = 0; e < DD; e++) {
            float ov = o_part[iw][0][e];
            float2 wv = __ldg(Wd2 + e * 32 + lane);
            f0 += ov * wv.x;
            f1 += ov * wv.y;
        }
        out[row * DD + d0]     = f0;
        out[row * DD + d0 + 1] = f1;
    }
}

// ---------------------------------------------------------------------------
// Inputs (metadata order): q, k, v, mask, Ww, wb, Wd, db, W1, b1, W2, b2
// Output: [out (B,H,LQ,D) | attn (B,H,LQ,LK)] as float32
// ---------------------------------------------------------------------------
extern "C" void kernel_launch(void* const* d_in, const int* in_sizes, int n_in,
                              void* d_out, int out_size)
{
    const float* q    = (const float*)d_in[0];
    const float* k    = (const float*)d_in[1];
    const float* v    = (const float*)d_in[2];
    const float* mask = (const float*)d_in[3];
    const float* Ww   = (const float*)d_in[4];
    const float* wb   = (const float*)d_in[5];
    const float* Wd   = (const float*)d_in[6];
    const float* db   = (const float*)d_in[7];
    const float* W1   = (const float*)d_in[8];
    const float* b1   = (const float*)d_in[9];
    const float* W2   = (const float*)d_in[10];
    const float* b2   = (const float*)d_in[11];
    float* out = (float*)d_out;

    prep_kernel<<<NB * (L / 4), 256>>>(q, k, v, Ww, wb, W1, b1);
    attn_kernel<<<NB * (L / 2), 256>>>(mask, Wd, db, W2, b2, out);
}